// round 16
// baseline (speedup 1.0000x reference)
#include <cuda_runtime.h>
#include <cuda_fp16.h>
#include <cstdint>
#include <cstddef>

// Problem constants (fixed for this problem; M derived at launch)
#define KDIM 4096
#define NDIM 11008
#define MMAX 8192
#define BM 128
#define BN 256
#define BK 128
#define STAGES 2
#define KT (KDIM / BK)        // 32
#define SA_STRIDE 136         // 128+8 halves -> 272B row stride (16B/row rotation, conflict-free)
#define SB_STRIDE 264         // 256+8 halves -> 528B row stride
#define A_STG (BM * SA_STRIDE)
#define B_STG (BK * SB_STRIDE)
#define DQ_BLOCKS ((NDIM / 64) * (KDIM / 256))   // 172*16 = 2752

// fp16 scratch: dequantized weights (scale folded), K-major [K][N]; fp16 copy of x.
static __device__ __half g_W[(size_t)KDIM * NDIM];   // 90.2 MB
static __device__ __half g_X[(size_t)MMAX * KDIM];   // 67.1 MB

// ---------------------------------------------------------------------------
// Phase 1 (fused): blocks [0, DQ_BLOCKS) dequantize packed ternary -> g_W;
// blocks [DQ_BLOCKS, ...) convert x f32->f16 -> g_X.
// Dequant math (proven bit-identical): 16-entry half2 LUT of exact (code-1)
// in {-1,0,+1}; hmul2 by fp16 scale gives {-s,0,+s} exactly.
// ---------------------------------------------------------------------------
__global__ __launch_bounds__(256) void prep_kernel(
    const float* __restrict__ x, const int32_t* __restrict__ pw,
    const float* __restrict__ scales, long long nx)
{
    __shared__ __half2 lut[16];
    __shared__ __half sw[256][72];   // row stride 144B (16B-aligned)
    const int t = threadIdx.x;

    if (blockIdx.x >= DQ_BLOCKS) {
        long long i = ((long long)(blockIdx.x - DQ_BLOCKS) * 256 + t) * 8;
        if (i + 8 <= nx) {
            float4 a = *reinterpret_cast<const float4*>(x + i);
            float4 b = *reinterpret_cast<const float4*>(x + i + 4);
            __half2 h[4];
            h[0] = __floats2half2_rn(a.x, a.y);
            h[1] = __floats2half2_rn(a.z, a.w);
            h[2] = __floats2half2_rn(b.x, b.y);
            h[3] = __floats2half2_rn(b.z, b.w);
            *reinterpret_cast<uint4*>(&g_X[i]) = *reinterpret_cast<uint4*>(h);
        }
        return;
    }

    const int n0  = (blockIdx.x % (NDIM / 64)) * 64;
    const int kp0 = (blockIdx.x / (NDIM / 64)) * 16;
    const int nl  = (t & 31) * 2;
    const int r0  = t >> 5;

    if (t < 16)
        lut[t] = __halves2half2(__int2half_rn((t & 3) - 1),
                                __int2half_rn((t >> 2) - 1));
    __syncthreads();

#pragma unroll
    for (int rr = r0; rr < 16; rr += 8) {
        const int kp = kp0 + rr;
        const int n  = n0 + nl;
        const int2  vab = *reinterpret_cast<const int2*>(&pw[(size_t)kp * NDIM + n]);
        const uint32_t va = (uint32_t)vab.x;
        const uint32_t vb = (uint32_t)vab.y;
        const int g = kp >> 3;
        const float2 sf = *reinterpret_cast<const float2*>(&scales[(size_t)g * NDIM + n]);
        const __half2 s2 = __floats2half2_rn(sf.x, sf.y);

        const uint32_t w1 = (va & 0x33333333u) | ((vb & 0x33333333u) << 2);
        const uint32_t w2 = ((va >> 2) & 0x33333333u) | (((vb >> 2) & 0x33333333u) << 2);

        __half* row_base = &sw[rr * 16][0];
#pragma unroll
        for (int m = 0; m < 8; m++) {
            const __half2 he = __hmul2(lut[(w1 >> (4 * m)) & 0xFu], s2);
            const __half2 ho = __hmul2(lut[(w2 >> (4 * m)) & 0xFu], s2);
            *reinterpret_cast<__half2*>(row_base + (2 * m) * 72 + nl)     = he;
            *reinterpret_cast<__half2*>(row_base + (2 * m + 1) * 72 + nl) = ho;
        }
    }
    __syncthreads();

#pragma unroll
    for (int i = t; i < 2048; i += 256) {
        const int row = i >> 3, c = i & 7;
        *reinterpret_cast<uint4*>(&g_W[(size_t)(kp0 * 16 + row) * NDIM + n0 + c * 8]) =
            *reinterpret_cast<const uint4*>(&sw[row][c * 8]);
    }
}

// ---------------------------------------------------------------------------
// Phase 2: persistent fp16 GEMM, fp32 acc. 128x256 tile, BK=128 with 2 smem
// stages: HALF the barrier count of the BK=64/4-stage version. Corrected
// loader maps: A covers 16 chunks/row, B covers 32 chunks/row. Load cursor
// leads compute by one 128-k iteration, seamless across tile boundaries.
// C_f32 = float( half(acc) + half(bias) ), reference rounding order.
// ---------------------------------------------------------------------------
#define CP_ASYNC16(dst, src) \
    asm volatile("cp.async.cg.shared.global [%0], [%1], 16;\n" :: "r"(dst), "l"(src))

__device__ __forceinline__ void tile_coords(int pid, int tiles_m, int tiles_n,
                                            int& m0, int& n0) {
    const int GROUPM = 16;
    const int per_group = GROUPM * tiles_n;
    const int gid = pid / per_group;
    const int first_m = gid * GROUPM;
    const int gsz = min(GROUPM, tiles_m - first_m);
    const int rr  = pid % per_group;
    m0 = (first_m + rr % gsz) * BM;
    n0 = (rr / gsz) * BN;
}

__global__ __launch_bounds__(256, 1) void gemm_kernel(
    const float* __restrict__ bias, float* __restrict__ C, int M)
{
    extern __shared__ __half smem[];
    __half* sA = smem;                      // [STAGES][BM][SA_STRIDE]
    __half* sB = smem + STAGES * A_STG;     // [STAGES][BK][SB_STRIDE]

    const int tiles_n = NDIM / BN;          // 43
    const int tiles_m = M / BM;             // 64
    const int NT = tiles_m * tiles_n;       // 2752
    const int step = gridDim.x;

    if ((int)blockIdx.x >= NT) return;
    const int nmine = (NT - 1 - (int)blockIdx.x) / step + 1;
    const int iters = nmine * KT;

    const int tid  = threadIdx.x;
    const int lane = tid & 31;
    const int warp = tid >> 5;
    const int wr = warp & 1;     // 0..1 -> 64-row slice
    const int wc = warp >> 1;    // 0..3 -> 64-col slice

    float acc[4][8][4];
#pragma unroll
    for (int a = 0; a < 4; a++)
#pragma unroll
        for (int b = 0; b < 8; b++)
#pragma unroll
            for (int c = 0; c < 4; c++) acc[a][b][c] = 0.f;

    const uint32_t sA_base = (uint32_t)__cvta_generic_to_shared(sA);
    const uint32_t sB_base = (uint32_t)__cvta_generic_to_shared(sB);

    // gmem->smem 16B-chunk coordinates (corrected for BK=128 / BN=256 rows).
    const int a_row = tid >> 4;           // 0..15; +16 per pass (4 passes per half)
    const int a_c   = (tid & 15) * 8;     // 16 chunks cover the full 128-half A row
    const int b_row = tid >> 5;           // 0..7;  +8 per pass (4 passes per part)
    const int b_c   = (tid & 31) * 8;     // 32 chunks cover the full 256-half B row

    // Compute-tile cursor (epilogue) and load-tile cursor (cp.async).
    int ctid = blockIdx.x, cm0, cn0;
    tile_coords(ctid, tiles_m, tiles_n, cm0, cn0);
    int ltid = ctid, lm0 = cm0, ln0 = cn0;
    const __half* lA = g_X + (size_t)(lm0 + a_row) * KDIM + a_c;
    const __half* lB = g_W + (size_t)b_row * NDIM + ln0 + b_c;

    auto load_A = [&](int stage, int kt, int half) {   // 64 rows per half
        uint32_t da = sA_base +
            (uint32_t)(stage * A_STG + (a_row + half * 64) * SA_STRIDE + a_c) * 2;
        const __half* ga = lA + kt * BK + (size_t)(half * 64) * KDIM;
#pragma unroll
        for (int i = 0; i < 4; i++) {
            CP_ASYNC16(da, ga);
            da += 16 * SA_STRIDE * 2;
            ga += (size_t)16 * KDIM;
        }
    };
    auto load_B = [&](int stage, int kt, int part) {   // 32 rows per part (0..3)
        uint32_t db = sB_base +
            (uint32_t)(stage * B_STG + (b_row + part * 32) * SB_STRIDE + b_c) * 2;
        const __half* gb = lB + (size_t)(kt * BK + part * 32) * NDIM;
#pragma unroll
        for (int i = 0; i < 4; i++) {
            CP_ASYNC16(db, gb);
            db += 8 * SB_STRIDE * 2;
            gb += (size_t)8 * NDIM;
        }
    };

    // ldmatrix lane-address components (proven mapping).
    const int lrow  = (lane & 7) + ((lane >> 3) & 1) * 8;
    const int acoff = ((lane >> 4) & 1) * 8;
    const int bkr   = (lane & 7) + ((lane >> 3) & 1) * 8;
    const int bnc   = wc * 64 + ((lane >> 4) & 1) * 8;

    uint32_t fa[2][4][4], fb[2][8][2];

    auto ldsm = [&](int stage, int ks, int buf) {
        const uint32_t pa = sA_base + (uint32_t)(stage * A_STG) * 2;
        const uint32_t pb = sB_base + (uint32_t)(stage * B_STG) * 2;
#pragma unroll
        for (int mi = 0; mi < 4; mi++) {
            const uint32_t addr = pa +
                (uint32_t)((wr * 64 + mi * 16 + lrow) * SA_STRIDE + ks * 16 + acoff) * 2;
            asm volatile("ldmatrix.sync.aligned.m8n8.x4.shared.b16 {%0,%1,%2,%3}, [%4];\n"
                : "=r"(fa[buf][mi][0]), "=r"(fa[buf][mi][1]),
                  "=r"(fa[buf][mi][2]), "=r"(fa[buf][mi][3])
                : "r"(addr));
        }
#pragma unroll
        for (int ng = 0; ng < 4; ng++) {
            const uint32_t addr = pb +
                (uint32_t)((ks * 16 + bkr) * SB_STRIDE + bnc + ng * 16) * 2;
            uint32_t r0, r1, r2, r3;
            asm volatile("ldmatrix.sync.aligned.m8n8.x4.trans.shared.b16 {%0,%1,%2,%3}, [%4];\n"
                : "=r"(r0), "=r"(r1), "=r"(r2), "=r"(r3) : "r"(addr));
            fb[buf][2 * ng][0] = r0;     fb[buf][2 * ng][1] = r1;
            fb[buf][2 * ng + 1][0] = r2; fb[buf][2 * ng + 1][1] = r3;
        }
    };

    auto mma_all = [&](int buf) {
#pragma unroll
        for (int mi = 0; mi < 4; mi++)
#pragma unroll
            for (int ni = 0; ni < 8; ni++) {
                asm volatile(
                    "mma.sync.aligned.m16n8k16.row.col.f32.f16.f16.f32 "
                    "{%0,%1,%2,%3}, {%4,%5,%6,%7}, {%8,%9}, {%0,%1,%2,%3};\n"
                    : "+f"(acc[mi][ni][0]), "+f"(acc[mi][ni][1]),
                      "+f"(acc[mi][ni][2]), "+f"(acc[mi][ni][3])
                    : "r"(fa[buf][mi][0]), "r"(fa[buf][mi][1]),
                      "r"(fa[buf][mi][2]), "r"(fa[buf][mi][3]),
                      "r"(fb[buf][ni][0]), "r"(fb[buf][ni][1]));
            }
    };

    // Prologue: load iteration 0 into stage 0, prime fragments.
    load_A(0, 0, 0);
    load_A(0, 0, 1);
#pragma unroll
    for (int p = 0; p < 4; p++) load_B(0, 0, p);
    asm volatile("cp.async.commit_group;\n");
    asm volatile("cp.async.wait_group 0;\n" ::: "memory");
    __syncthreads();
    ldsm(0, 0, 0);

    for (int ci = 0; ci < iters; ci++) {
        const int stage = ci & 1;
        const int li = ci + 1;
        const bool do_load = li < iters;
        const int lstage = li & 1;
        const int lkt = li & (KT - 1);
#pragma unroll
        for (int ks = 0; ks < 8; ks++) {
            const int cur = ks & 1, nxt = cur ^ 1;
            if (do_load) {
                if (ks == 0) {
                    if (lkt == 0) {   // load cursor crosses into next tile
                        ltid += step;
                        tile_coords(ltid, tiles_m, tiles_n, lm0, ln0);
                        lA = g_X + (size_t)(lm0 + a_row) * KDIM + a_c;
                        lB = g_W + (size_t)b_row * NDIM + ln0 + b_c;
                    }
                    load_A(lstage, lkt, 0);
                }
                if (ks == 1) load_A(lstage, lkt, 1);
                if (ks >= 2 && ks <= 5) load_B(lstage, lkt, ks - 2);
            }
            if (ks == 6)
                asm volatile("cp.async.commit_group;\n");   // one group per ci
            if (ks < 7) {
                ldsm(stage, ks + 1, nxt);
                mma_all(cur);
            } else {
                mma_all(cur);   // feed the pipe before the barrier
                asm volatile("cp.async.wait_group 0;\n" ::: "memory");
                __syncthreads();
                if (ci + 1 < iters) ldsm(lstage, 0, nxt);
            }
        }

        if ((ci & (KT - 1)) == KT - 1) {
            // Epilogue for the finished tile; next tile's loads are in flight.
#pragma unroll
            for (int mi = 0; mi < 4; mi++) {
                const int row = cm0 + wr * 64 + mi * 16 + (lane >> 2);
#pragma unroll
                for (int ni = 0; ni < 8; ni++) {
                    const int col = cn0 + wc * 64 + ni * 8 + (lane & 3) * 2;
                    const float2 bf32 = *reinterpret_cast<const float2*>(bias + col);
                    const __half2 bv = __floats2half2_rn(bf32.x, bf32.y);
                    __half2 v0 = __hadd2(__floats2half2_rn(acc[mi][ni][0], acc[mi][ni][1]), bv);
                    __half2 v1 = __hadd2(__floats2half2_rn(acc[mi][ni][2], acc[mi][ni][3]), bv);
                    float2 o0 = __half22float2(v0);
                    float2 o1 = __half22float2(v1);
                    *reinterpret_cast<float2*>(C + (size_t)row * NDIM + col) = o0;
                    *reinterpret_cast<float2*>(C + (size_t)(row + 8) * NDIM + col) = o1;
#pragma unroll
                    for (int c = 0; c < 4; c++) acc[mi][ni][c] = 0.f;
                }
            }
            ctid += step;
            if (ctid < NT) tile_coords(ctid, tiles_m, tiles_n, cm0, cn0);
        }
    }
}

// ---------------------------------------------------------------------------
extern "C" void kernel_launch(void* const* d_in, const int* in_sizes, int n_in,
                              void* d_out, int out_size) {
    const float*   x      = (const float*)d_in[0];
    const int32_t* pw     = (const int32_t*)d_in[1];
    const float*   scales = (const float*)d_in[2];
    const float*   bias   = (const float*)d_in[3];
    float*         out    = (float*)d_out;
    const int M = in_sizes[0] / KDIM;   // 8192

    const long long nx = (long long)M * KDIM;
    const int cv_blocks = (int)((nx / 8 + 255) / 256);
    prep_kernel<<<DQ_BLOCKS + cv_blocks, 256>>>(x, pw, scales, nx);

    int sm_count = 148;
    cudaDeviceGetAttribute(&sm_count, cudaDevAttrMultiProcessorCount, 0);
    const int NT = (M / BM) * (NDIM / BN);   // 2752
    const int grid = (sm_count < NT) ? sm_count : NT;

    const int smem_bytes = STAGES * (A_STG + B_STG) * (int)sizeof(__half);  // 204800
    cudaFuncSetAttribute(gemm_kernel, cudaFuncAttributeMaxDynamicSharedMemorySize,
                         smem_bytes);
    gemm_kernel<<<grid, 256, smem_bytes>>>(bias, out, M);
}

// round 17
// speedup vs baseline: 1.0986x; 1.0986x over previous
#include <cuda_runtime.h>
#include <cuda_fp16.h>
#include <cstdint>
#include <cstddef>

// Problem constants (fixed for this problem; M derived at launch)
#define KDIM 4096
#define NDIM 11008
#define MMAX 8192
#define BM 128
#define BN 256
#define BK 64
#define STAGES 4
#define KT (KDIM / BK)        // 64
#define SA_STRIDE 72          // 64+8 halves -> 144B row stride (conflict-free ldmatrix)
#define SB_STRIDE 264         // 256+8 halves -> 528B row stride
#define A_STG (BM * SA_STRIDE)
#define B_STG (BK * SB_STRIDE)
#define DQ_BLOCKS ((NDIM / 64) * (KDIM / 256))   // 172*16 = 2752

// fp16 scratch: dequantized weights (scale folded), K-major [K][N]; fp16 copy of x.
static __device__ __half g_W[(size_t)KDIM * NDIM];   // 90.2 MB
static __device__ __half g_X[(size_t)MMAX * KDIM];   // 67.1 MB

// ---------------------------------------------------------------------------
// Phase 1 (fused): blocks [0, DQ_BLOCKS) dequantize packed ternary -> g_W;
// blocks [DQ_BLOCKS, ...) convert x f32->f16 -> g_X.
// Dequant math (proven bit-identical): 16-entry half2 LUT of exact (code-1)
// in {-1,0,+1}; hmul2 by fp16 scale gives {-s,0,+s} exactly.
// ---------------------------------------------------------------------------
__global__ __launch_bounds__(256) void prep_kernel(
    const float* __restrict__ x, const int32_t* __restrict__ pw,
    const float* __restrict__ scales, long long nx)
{
    __shared__ __half2 lut[16];
    __shared__ __half sw[256][72];   // row stride 144B (16B-aligned)
    const int t = threadIdx.x;

    if (blockIdx.x >= DQ_BLOCKS) {
        long long i = ((long long)(blockIdx.x - DQ_BLOCKS) * 256 + t) * 8;
        if (i + 8 <= nx) {
            float4 a = *reinterpret_cast<const float4*>(x + i);
            float4 b = *reinterpret_cast<const float4*>(x + i + 4);
            __half2 h[4];
            h[0] = __floats2half2_rn(a.x, a.y);
            h[1] = __floats2half2_rn(a.z, a.w);
            h[2] = __floats2half2_rn(b.x, b.y);
            h[3] = __floats2half2_rn(b.z, b.w);
            *reinterpret_cast<uint4*>(&g_X[i]) = *reinterpret_cast<uint4*>(h);
        }
        return;
    }

    const int n0  = (blockIdx.x % (NDIM / 64)) * 64;
    const int kp0 = (blockIdx.x / (NDIM / 64)) * 16;
    const int nl  = (t & 31) * 2;
    const int r0  = t >> 5;

    if (t < 16)
        lut[t] = __halves2half2(__int2half_rn((t & 3) - 1),
                                __int2half_rn((t >> 2) - 1));
    __syncthreads();

#pragma unroll
    for (int rr = r0; rr < 16; rr += 8) {
        const int kp = kp0 + rr;
        const int n  = n0 + nl;
        const int2  vab = *reinterpret_cast<const int2*>(&pw[(size_t)kp * NDIM + n]);
        const uint32_t va = (uint32_t)vab.x;
        const uint32_t vb = (uint32_t)vab.y;
        const int g = kp >> 3;
        const float2 sf = *reinterpret_cast<const float2*>(&scales[(size_t)g * NDIM + n]);
        const __half2 s2 = __floats2half2_rn(sf.x, sf.y);

        const uint32_t w1 = (va & 0x33333333u) | ((vb & 0x33333333u) << 2);
        const uint32_t w2 = ((va >> 2) & 0x33333333u) | (((vb >> 2) & 0x33333333u) << 2);

        __half* row_base = &sw[rr * 16][0];
#pragma unroll
        for (int m = 0; m < 8; m++) {
            const __half2 he = __hmul2(lut[(w1 >> (4 * m)) & 0xFu], s2);
            const __half2 ho = __hmul2(lut[(w2 >> (4 * m)) & 0xFu], s2);
            *reinterpret_cast<__half2*>(row_base + (2 * m) * 72 + nl)     = he;
            *reinterpret_cast<__half2*>(row_base + (2 * m + 1) * 72 + nl) = ho;
        }
    }
    __syncthreads();

#pragma unroll
    for (int i = t; i < 2048; i += 256) {
        const int row = i >> 3, c = i & 7;
        *reinterpret_cast<uint4*>(&g_W[(size_t)(kp0 * 16 + row) * NDIM + n0 + c * 8]) =
            *reinterpret_cast<const uint4*>(&sw[row][c * 8]);
    }
}

// ---------------------------------------------------------------------------
// Phase 2: persistent fp16 GEMM, fp32 acc. R13 mainloop (128x256, BK=64,
// 4 stages, double-buffered fragments, persistent cross-tile load cursor)
// restructured into ITERATION PAIRS: one __syncthreads per 2 k-iterations
// (stage-reuse safety), mid-pair RAW hazard covered by cp.async.wait_group 1
// (cheap, per-thread). One commit group per iteration at ks2; at every wait
// exactly 2 groups pending, the older (issued >=5 ks earlier) is complete.
// C_f32 = float( half(acc) + half(bias) ), reference rounding order.
// ---------------------------------------------------------------------------
#define CP_ASYNC16(dst, src) \
    asm volatile("cp.async.cg.shared.global [%0], [%1], 16;\n" :: "r"(dst), "l"(src))

__device__ __forceinline__ void tile_coords(int pid, int tiles_m, int tiles_n,
                                            int& m0, int& n0) {
    const int GROUPM = 16;
    const int per_group = GROUPM * tiles_n;
    const int gid = pid / per_group;
    const int first_m = gid * GROUPM;
    const int gsz = min(GROUPM, tiles_m - first_m);
    const int rr  = pid % per_group;
    m0 = (first_m + rr % gsz) * BM;
    n0 = (rr / gsz) * BN;
}

__global__ __launch_bounds__(256, 1) void gemm_kernel(
    const float* __restrict__ bias, float* __restrict__ C, int M)
{
    extern __shared__ __half smem[];
    __half* sA = smem;                      // [STAGES][BM][SA_STRIDE]
    __half* sB = smem + STAGES * A_STG;     // [STAGES][BK][SB_STRIDE]

    const int tiles_n = NDIM / BN;          // 43
    const int tiles_m = M / BM;             // 64
    const int NT = tiles_m * tiles_n;       // 2752
    const int step = gridDim.x;

    if ((int)blockIdx.x >= NT) return;
    const int nmine = (NT - 1 - (int)blockIdx.x) / step + 1;
    const int iters = nmine * KT;           // even (KT=64)

    const int tid  = threadIdx.x;
    const int lane = tid & 31;
    const int warp = tid >> 5;
    const int wr = warp & 1;     // 0..1 -> 64-row slice
    const int wc = warp >> 1;    // 0..3 -> 64-col slice

    float acc[4][8][4];
#pragma unroll
    for (int a = 0; a < 4; a++)
#pragma unroll
        for (int b = 0; b < 8; b++)
#pragma unroll
            for (int c = 0; c < 4; c++) acc[a][b][c] = 0.f;

    const uint32_t sA_base = (uint32_t)__cvta_generic_to_shared(sA);
    const uint32_t sB_base = (uint32_t)__cvta_generic_to_shared(sB);

    // gmem->smem 16B-chunk coordinates.
    const int a_row = tid >> 3;           // +32/iter (4 iters)
    const int a_c   = (tid & 7) * 8;
    const int b_row = tid >> 5;           // +8/iter (4 iters x 2 halves)
    const int b_c   = (tid & 31) * 8;

    // Compute-tile cursor (epilogue) and load-tile cursor (cp.async).
    int ctid = blockIdx.x, cm0, cn0;
    tile_coords(ctid, tiles_m, tiles_n, cm0, cn0);
    int ltid = ctid, lm0, ln0;
    const __half* lA = g_X + (size_t)(cm0 + a_row) * KDIM + a_c;
    const __half* lB = g_W + (size_t)b_row * NDIM + cn0 + b_c;

    auto load_A = [&](int stage, int kt) {
        uint32_t da = sA_base + (uint32_t)(stage * A_STG + a_row * SA_STRIDE + a_c) * 2;
        const __half* ga = lA + kt * BK;
#pragma unroll
        for (int i = 0; i < 4; i++) {
            CP_ASYNC16(da, ga);
            da += 32 * SA_STRIDE * 2;
            ga += (size_t)32 * KDIM;
        }
    };
    auto load_B = [&](int stage, int kt, int half) {
        uint32_t db = sB_base + (uint32_t)(stage * B_STG + (b_row + half * 32) * SB_STRIDE + b_c) * 2;
        const __half* gb = lB + (size_t)(kt * BK + half * 32) * NDIM;
#pragma unroll
        for (int i = 0; i < 4; i++) {
            CP_ASYNC16(db, gb);
            db += 8 * SB_STRIDE * 2;
            gb += (size_t)8 * NDIM;
        }
    };
    auto advance_load_cursor = [&](int li, int lkt) {
        if (lkt == 0 && li >= KT) {       // load cursor crosses into next tile
            ltid += step;
            tile_coords(ltid, tiles_m, tiles_n, lm0, ln0);
            lA = g_X + (size_t)(lm0 + a_row) * KDIM + a_c;
            lB = g_W + (size_t)b_row * NDIM + ln0 + b_c;
        }
    };

    // ldmatrix lane-address components (R11/R13-proven mapping).
    const int lrow  = (lane & 7) + ((lane >> 3) & 1) * 8;
    const int acoff = ((lane >> 4) & 1) * 8;
    const int bkr   = (lane & 7) + ((lane >> 3) & 1) * 8;
    const int bnc   = wc * 64 + ((lane >> 4) & 1) * 8;

    uint32_t fa[2][4][4], fb[2][8][2];

    auto ldsm = [&](int stage, int ks, int buf) {
        const uint32_t pa = sA_base + (uint32_t)(stage * A_STG) * 2;
        const uint32_t pb = sB_base + (uint32_t)(stage * B_STG) * 2;
#pragma unroll
        for (int mi = 0; mi < 4; mi++) {
            const uint32_t addr = pa +
                (uint32_t)((wr * 64 + mi * 16 + lrow) * SA_STRIDE + ks * 16 + acoff) * 2;
            asm volatile("ldmatrix.sync.aligned.m8n8.x4.shared.b16 {%0,%1,%2,%3}, [%4];\n"
                : "=r"(fa[buf][mi][0]), "=r"(fa[buf][mi][1]),
                  "=r"(fa[buf][mi][2]), "=r"(fa[buf][mi][3])
                : "r"(addr));
        }
#pragma unroll
        for (int ng = 0; ng < 4; ng++) {
            const uint32_t addr = pb +
                (uint32_t)((ks * 16 + bkr) * SB_STRIDE + bnc + ng * 16) * 2;
            uint32_t r0, r1, r2, r3;
            asm volatile("ldmatrix.sync.aligned.m8n8.x4.trans.shared.b16 {%0,%1,%2,%3}, [%4];\n"
                : "=r"(r0), "=r"(r1), "=r"(r2), "=r"(r3) : "r"(addr));
            fb[buf][2 * ng][0] = r0;     fb[buf][2 * ng][1] = r1;
            fb[buf][2 * ng + 1][0] = r2; fb[buf][2 * ng + 1][1] = r3;
        }
    };

    auto mma_all = [&](int buf) {
#pragma unroll
        for (int mi = 0; mi < 4; mi++)
#pragma unroll
            for (int ni = 0; ni < 8; ni++) {
                asm volatile(
                    "mma.sync.aligned.m16n8k16.row.col.f32.f16.f16.f32 "
                    "{%0,%1,%2,%3}, {%4,%5,%6,%7}, {%8,%9}, {%0,%1,%2,%3};\n"
                    : "+f"(acc[mi][ni][0]), "+f"(acc[mi][ni][1]),
                      "+f"(acc[mi][ni][2]), "+f"(acc[mi][ni][3])
                    : "r"(fa[buf][mi][0]), "r"(fa[buf][mi][1]),
                      "r"(fa[buf][mi][2]), "r"(fa[buf][mi][3]),
                      "r"(fb[buf][ni][0]), "r"(fb[buf][ni][1]));
            }
    };

    // Prologue: iter 0 -> stage 0 (group G0), iter 1 -> stage 1 (group G1).
    load_A(0, 0); load_B(0, 0, 0); load_B(0, 0, 1);
    asm volatile("cp.async.commit_group;\n");
    load_A(1, 1); load_B(1, 1, 0); load_B(1, 1, 1);
    asm volatile("cp.async.commit_group;\n");
    asm volatile("cp.async.wait_group 1;\n" ::: "memory");   // G0 done
    __syncthreads();
    ldsm(0, 0, 0);

    for (int ci = 0; ci < iters; ci += 2) {
        // ---- iteration A: compute ci (stage ci&3); load li0 = ci+2 ----
        {
            const int stage = ci & (STAGES - 1);
            const int li = ci + 2;
            const bool dl = li < iters;
            const int ls = li & (STAGES - 1);
            const int lkt = li & (KT - 1);
#pragma unroll
            for (int ks = 0; ks < 4; ks++) {
                const int cur = ks & 1, nxt = cur ^ 1;
                if (ks == 0 && dl) { advance_load_cursor(li, lkt); load_A(ls, lkt); }
                if (ks == 1 && dl) load_B(ls, lkt, 0);
                if (ks == 2) {
                    if (dl) load_B(ls, lkt, 1);
                    asm volatile("cp.async.commit_group;\n");   // one group per iter
                }
                if (ks < 3) {
                    ldsm(stage, ks + 1, nxt);
                    mma_all(cur);
                } else {
                    mma_all(cur);
                    // cheap RAW wait: ensure iter ci+1's group done (2 pending).
                    asm volatile("cp.async.wait_group 1;\n" ::: "memory");
                    ldsm((ci + 1) & (STAGES - 1), 0, nxt);
                }
            }
        }
        // ---- iteration B: compute ci+1 (stage (ci+1)&3); load li1 = ci+3 ----
        {
            const int cb = ci + 1;
            const int stage = cb & (STAGES - 1);
            const int li = cb + 2;
            const bool dl = li < iters;
            const int ls = li & (STAGES - 1);
            const int lkt = li & (KT - 1);
#pragma unroll
            for (int ks = 0; ks < 4; ks++) {
                const int cur = ks & 1, nxt = cur ^ 1;
                if (ks == 0 && dl) { advance_load_cursor(li, lkt); load_A(ls, lkt); }
                if (ks == 1 && dl) load_B(ls, lkt, 0);
                if (ks == 2) {
                    if (dl) load_B(ls, lkt, 1);
                    asm volatile("cp.async.commit_group;\n");
                }
                if (ks < 3) {
                    ldsm(stage, ks + 1, nxt);
                    mma_all(cur);
                } else {
                    mma_all(cur);
                    asm volatile("cp.async.wait_group 1;\n" ::: "memory");
                    __syncthreads();   // stage-reuse barrier: once per PAIR
                    if (ci + 2 < iters) ldsm((ci + 2) & (STAGES - 1), 0, nxt);
                }
            }
        }

        if (((ci + 1) & (KT - 1)) == KT - 1) {
            // Epilogue for the finished tile; next tile's loads are in flight.
#pragma unroll
            for (int mi = 0; mi < 4; mi++) {
                const int row = cm0 + wr * 64 + mi * 16 + (lane >> 2);
#pragma unroll
                for (int ni = 0; ni < 8; ni++) {
                    const int col = cn0 + wc * 64 + ni * 8 + (lane & 3) * 2;
                    const float2 bf32 = *reinterpret_cast<const float2*>(bias + col);
                    const __half2 bv = __floats2half2_rn(bf32.x, bf32.y);
                    __half2 v0 = __hadd2(__floats2half2_rn(acc[mi][ni][0], acc[mi][ni][1]), bv);
                    __half2 v1 = __hadd2(__floats2half2_rn(acc[mi][ni][2], acc[mi][ni][3]), bv);
                    float2 o0 = __half22float2(v0);
                    float2 o1 = __half22float2(v1);
                    *reinterpret_cast<float2*>(C + (size_t)row * NDIM + col) = o0;
                    *reinterpret_cast<float2*>(C + (size_t)(row + 8) * NDIM + col) = o1;
#pragma unroll
                    for (int c = 0; c < 4; c++) acc[mi][ni][c] = 0.f;
                }
            }
            ctid += step;
            if (ctid < NT) tile_coords(ctid, tiles_m, tiles_n, cm0, cn0);
        }
    }
}

// ---------------------------------------------------------------------------
extern "C" void kernel_launch(void* const* d_in, const int* in_sizes, int n_in,
                              void* d_out, int out_size) {
    const float*   x      = (const float*)d_in[0];
    const int32_t* pw     = (const int32_t*)d_in[1];
    const float*   scales = (const float*)d_in[2];
    const float*   bias   = (const float*)d_in[3];
    float*         out    = (float*)d_out;
    const int M = in_sizes[0] / KDIM;   // 8192

    const long long nx = (long long)M * KDIM;
    const int cv_blocks = (int)((nx / 8 + 255) / 256);
    prep_kernel<<<DQ_BLOCKS + cv_blocks, 256>>>(x, pw, scales, nx);

    int sm_count = 148;
    cudaDeviceGetAttribute(&sm_count, cudaDevAttrMultiProcessorCount, 0);
    const int NT = (M / BM) * (NDIM / BN);   // 2752
    const int grid = (sm_count < NT) ? sm_count : NT;

    const int smem_bytes = STAGES * (A_STG + B_STG) * (int)sizeof(__half);  // 208896
    cudaFuncSetAttribute(gemm_kernel, cudaFuncAttributeMaxDynamicSharedMemorySize,
                         smem_bytes);
    gemm_kernel<<<grid, 256, smem_bytes>>>(bias, out, M);
}